// round 4
// baseline (speedup 1.0000x reference)
#include <cuda_runtime.h>
#include <math.h>

#define BB 64
#define TT 20
#define EE 512
#define VV 32000
#define G4 2048   // 4*EE

// ---------------- scratch (no allocations allowed) ----------------
__device__ float g_emb[TT * BB * EE];   // [t][b][e]  embeddings
__device__ float g_seq[BB * TT * EE];   // [b][t][e]  == row-major [M=1280][512]
__device__ float g_h[BB * EE];
__device__ float g_c[BB * EE];
__device__ float g_gates[BB * G4];      // [b][4E] accumulator (split-K atomics)

// ---------------- embedding gather + seq row 0 ----------------
__global__ void gather_kernel(const int* __restrict__ captions,
                              const float* __restrict__ W_emb) {
    int idx = blockIdx.x * blockDim.x + threadIdx.x;
    if (idx >= TT * BB * EE) return;
    int e = idx % EE;
    int b = (idx / EE) % BB;
    int t = idx / (EE * BB);
    float v = W_emb[(size_t)captions[b * TT + t] * EE + e];
    g_emb[idx] = v;
    if (t == 0) g_seq[(size_t)(b * TT) * EE + e] = v;   // seq[:,0] = emb[:,0]
}

// ---------------- h = 0, c = features, gates = 0 ----------------
__global__ void init_state_kernel(const float* __restrict__ features) {
    int idx = blockIdx.x * blockDim.x + threadIdx.x;
    if (idx < BB * EE) { g_h[idx] = 0.f; g_c[idx] = features[idx]; }
    if (idx < BB * G4) g_gates[idx] = 0.f;
}

// ---------------- LSTM step GEMM (split-K=4, atomic accumulate) ----------------
// gates[64,2048] += chunk of  x @ W_ih^T  (ksplit 0,1)  or  h @ W_hh^T (ksplit 2,3)
// block: 64 batch x 64 cols tile, K-range of 256. 32 n-tiles * 4 splits = 128 blocks.
__global__ __launch_bounds__(256) void lstm_gemm_kernel(
        const float* __restrict__ W_ih, const float* __restrict__ W_hh, int t) {
    __shared__ float Xs[64][36];  // +4 pad: kills LDS.128 bank conflicts
    __shared__ float Ws[64][36];

    int n0 = blockIdx.x * 64;
    int ks = blockIdx.y;                 // 0..3
    const float* __restrict__ xsrc;
    const float* __restrict__ wsrc;
    int koff;
    if (ks < 2) { xsrc = g_emb + (size_t)(t - 1) * BB * EE; wsrc = W_ih; koff = ks * 256; }
    else        { xsrc = g_h;                               wsrc = W_hh; koff = (ks - 2) * 256; }

    int tid = threadIdx.x;
    int tx = tid & 15;   // col group (4 cols)
    int ty = tid >> 4;   // batch group (4 rows)
    float acc[4][4] = {};

    for (int kc = 0; kc < 256; kc += 32) {
#pragma unroll
        for (int i = 0; i < 2; i++) {
            int q = tid + i * 256;            // 0..511 float4 slots
            int r = q >> 3;                   // 0..63
            int kk = (q & 7) << 2;            // 0..28
            float4 xv = *(const float4*)(xsrc + (size_t)r * EE + koff + kc + kk);
            *(float4*)(&Xs[r][kk]) = xv;
            float4 wv = *(const float4*)(wsrc + (size_t)(n0 + r) * EE + koff + kc + kk);
            *(float4*)(&Ws[r][kk]) = wv;
        }
        __syncthreads();
#pragma unroll
        for (int k4 = 0; k4 < 8; k4++) {
            float4 xr[4], wr[4];
#pragma unroll
            for (int i = 0; i < 4; i++) xr[i] = *(const float4*)(&Xs[ty * 4 + i][k4 * 4]);
#pragma unroll
            for (int j = 0; j < 4; j++) wr[j] = *(const float4*)(&Ws[tx * 4 + j][k4 * 4]);
#pragma unroll
            for (int i = 0; i < 4; i++)
#pragma unroll
                for (int j = 0; j < 4; j++)
                    acc[i][j] += xr[i].x * wr[j].x + xr[i].y * wr[j].y
                               + xr[i].z * wr[j].z + xr[i].w * wr[j].w;
        }
        __syncthreads();
    }
#pragma unroll
    for (int i = 0; i < 4; i++)
#pragma unroll
        for (int j = 0; j < 4; j++)
            atomicAdd(&g_gates[(size_t)(ty * 4 + i) * G4 + n0 + tx * 4 + j], acc[i][j]);
}

// ---------------- LSTM gate activations + state update ----------------
// Also re-zeros the gate accumulator for the next step's atomics.
__global__ void lstm_pointwise_kernel(const float* __restrict__ b_ih,
                                      const float* __restrict__ b_hh, int t) {
    int idx = blockIdx.x * blockDim.x + threadIdx.x;   // < BB*EE
    if (idx >= BB * EE) return;
    int b = idx / EE, n = idx % EE;
    float* gp = &g_gates[(size_t)b * G4 + n];
    float gi = gp[0]        + b_ih[n]          + b_hh[n];
    float gf = gp[EE]       + b_ih[EE + n]     + b_hh[EE + n];
    float gg = gp[2 * EE]   + b_ih[2 * EE + n] + b_hh[2 * EE + n];
    float go = gp[3 * EE]   + b_ih[3 * EE + n] + b_hh[3 * EE + n];
    gp[0] = 0.f; gp[EE] = 0.f; gp[2 * EE] = 0.f; gp[3 * EE] = 0.f;

    float iv = 1.f / (1.f + expf(-gi));
    float fv = 1.f / (1.f + expf(-gf));
    float gv = tanhf(gg);
    float ov = 1.f / (1.f + expf(-go));
    float c  = fv * g_c[idx] + iv * gv;
    g_c[idx] = c;
    float h  = ov * tanhf(c);
    g_h[idx] = h;
    g_seq[((size_t)b * TT + t) * EE + n] = h;
}

// ---------------- output projection: [1280,512] @ [512,32000] + bias ----------------
// 128x128 tiles, BK=16, 256 threads, 8x8 register blocking.
__global__ __launch_bounds__(256) void proj_kernel(
        const float* __restrict__ W_out, const float* __restrict__ b_out,
        float* __restrict__ out) {
    __shared__ float As[16][132];   // [k][m], +4 pad (132*4B = 33*16B, keeps f4 align)
    __shared__ float Bs[16][132];   // [k][n]

    int tid = threadIdx.x;
    int tn = tid & 15;
    int tm = tid >> 4;
    int m0 = blockIdx.y * 128;
    int n0 = blockIdx.x * 128;
    float acc[8][8] = {};

    for (int kc = 0; kc < EE; kc += 16) {
#pragma unroll
        for (int i = 0; i < 2; i++) {
            int q = tid + i * 256;           // 0..511 float4 slots
            int r = q >> 2;                  // 0..127
            int kk = (q & 3) << 2;           // 0,4,8,12
            float4 av = *(const float4*)(g_seq + (size_t)(m0 + r) * EE + kc + kk);
            As[kk + 0][r] = av.x; As[kk + 1][r] = av.y;
            As[kk + 2][r] = av.z; As[kk + 3][r] = av.w;
            float4 bv = *(const float4*)(W_out + (size_t)(n0 + r) * EE + kc + kk);
            Bs[kk + 0][r] = bv.x; Bs[kk + 1][r] = bv.y;
            Bs[kk + 2][r] = bv.z; Bs[kk + 3][r] = bv.w;
        }
        __syncthreads();
#pragma unroll
        for (int k = 0; k < 16; k++) {
            float aR[8], bR[8];
            *(float4*)&aR[0] = *(const float4*)(&As[k][tm * 8]);
            *(float4*)&aR[4] = *(const float4*)(&As[k][tm * 8 + 4]);
            *(float4*)&bR[0] = *(const float4*)(&Bs[k][tn * 8]);
            *(float4*)&bR[4] = *(const float4*)(&Bs[k][tn * 8 + 4]);
#pragma unroll
            for (int i = 0; i < 8; i++)
#pragma unroll
                for (int j = 0; j < 8; j++)
                    acc[i][j] += aR[i] * bR[j];
        }
        __syncthreads();
    }
#pragma unroll
    for (int i = 0; i < 8; i++) {
        int m = m0 + tm * 8 + i;
        float* orow = out + (size_t)m * VV + n0 + tn * 8;
#pragma unroll
        for (int j = 0; j < 8; j += 4) {
            float4 v;
            v.x = acc[i][j + 0] + b_out[n0 + tn * 8 + j + 0];
            v.y = acc[i][j + 1] + b_out[n0 + tn * 8 + j + 1];
            v.z = acc[i][j + 2] + b_out[n0 + tn * 8 + j + 2];
            v.w = acc[i][j + 3] + b_out[n0 + tn * 8 + j + 3];
            *(float4*)(orow + j) = v;
        }
    }
}

// ---------------- launch ----------------
extern "C" void kernel_launch(void* const* d_in, const int* in_sizes, int n_in,
                              void* d_out, int out_size) {
    const float* features = (const float*)d_in[0];
    const int*   captions = (const int*)d_in[1];
    const float* W_emb    = (const float*)d_in[2];
    const float* W_out    = (const float*)d_in[3];
    const float* b_out    = (const float*)d_in[4];
    const float* W_ih     = (const float*)d_in[5];
    const float* W_hh     = (const float*)d_in[6];
    const float* b_ih     = (const float*)d_in[7];
    const float* b_hh     = (const float*)d_in[8];
    float* out = (float*)d_out;

    gather_kernel<<<(TT * BB * EE + 255) / 256, 256>>>(captions, W_emb);
    init_state_kernel<<<(BB * G4 + 255) / 256, 256>>>(features);

    for (int t = 1; t < TT; t++) {
        lstm_gemm_kernel<<<dim3(32, 4), 256>>>(W_ih, W_hh, t);
        lstm_pointwise_kernel<<<(BB * EE + 255) / 256, 256>>>(b_ih, b_hh, t);
    }

    proj_kernel<<<dim3(VV / 128, (BB * TT) / 128), 256>>>(W_out, b_out, out);
}

// round 7
// speedup vs baseline: 1.8192x; 1.8192x over previous
#include <cuda_runtime.h>
#include <cuda_bf16.h>
#include <math.h>
#include <stdint.h>

#define BB 64
#define TT 20
#define EE 512
#define VV 32000
#define G4 2048   // 4*EE
#define NSTEP (TT - 1)

// ---------------- scratch (no allocations allowed) ----------------
__device__ float g_h[BB * EE];
__device__ float g_c[BB * EE];
__device__ float g_xgates[NSTEP * BB * G4];      // [(t-1)*64+b][4E]
__device__ unsigned g_bars[64];                  // grid-barrier slots (zeroed per call)
__device__ __nv_bfloat16 g_Ehi[TT * BB * EE];    // emb split [t*64+b][e]
__device__ __nv_bfloat16 g_Elo[TT * BB * EE];
__device__ __nv_bfloat16 g_Shi[BB * TT * EE];    // seq split [b*20+t][e] (proj A operand)
__device__ __nv_bfloat16 g_Slo[BB * TT * EE];
__device__ __nv_bfloat16 g_WoutHi[(size_t)VV * EE];
__device__ __nv_bfloat16 g_WoutLo[(size_t)VV * EE];
__device__ __nv_bfloat16 g_WihHi[G4 * EE];
__device__ __nv_bfloat16 g_WihLo[G4 * EE];

// ================= helpers =================
__device__ __forceinline__ uint32_t smem_u32(const void* p) {
    uint32_t a;
    asm("{ .reg .u64 t; cvta.to.shared.u64 t, %1; cvt.u32.u64 %0, t; }" : "=r"(a) : "l"(p));
    return a;
}
__device__ __forceinline__ void bf16_split(float v, __nv_bfloat16& h, __nv_bfloat16& l) {
    h = __float2bfloat16(v);
    l = __float2bfloat16(v - __bfloat162float(h));
}

#define LDSM4(r, a)                                                            \
    asm volatile("ldmatrix.sync.aligned.m8n8.x4.shared.b16 {%0,%1,%2,%3}, [%4];" \
        : "=r"((r)[0]), "=r"((r)[1]), "=r"((r)[2]), "=r"((r)[3]) : "r"(a))
#define LDSM2(r, a)                                                            \
    asm volatile("ldmatrix.sync.aligned.m8n8.x2.shared.b16 {%0,%1}, [%2];"     \
        : "=r"((r)[0]), "=r"((r)[1]) : "r"(a))
#define MMA_BF16(acc, a, b)                                                    \
    asm volatile("mma.sync.aligned.m16n8k16.row.col.f32.bf16.bf16.f32 "        \
        "{%0,%1,%2,%3}, {%4,%5,%6,%7}, {%8,%9}, {%0,%1,%2,%3};"                \
        : "+f"((acc)[0]), "+f"((acc)[1]), "+f"((acc)[2]), "+f"((acc)[3])       \
        : "r"((a)[0]), "r"((a)[1]), "r"((a)[2]), "r"((a)[3]),                  \
          "r"((b)[0]), "r"((b)[1]))
#define CP_ASYNC16(sp, gp)                                                     \
    asm volatile("cp.async.ca.shared.global [%0], [%1], 16;" :: "r"(sp), "l"(gp))

// ================= HMMA bf16-split GEMM =================
// C[m0:128, n0:128] = Ahi*Bhi + Ahi*Blo + Alo*Bhi  (A [*,512] row-major, B [N,512] row-major)
// K = 512 fixed. bias1 (+bias2) added. Store guarded by m < mrows.
#define BK 32
#define SR 80                  // smem row stride bytes (64B data + 16B pad)
#define OPB (128 * SR)         // bytes per operand tile (10240)
#define BUFB (4 * OPB)         // per buffer (40960)
#define SMEMB (2 * BUFB)       // 81920

__global__ __launch_bounds__(256) void hmma_gemm_kernel(
        const __nv_bfloat16* __restrict__ Ahi, const __nv_bfloat16* __restrict__ Alo,
        const __nv_bfloat16* __restrict__ Bhi, const __nv_bfloat16* __restrict__ Blo,
        float* __restrict__ C, int ldc,
        const float* __restrict__ bias1, const float* __restrict__ bias2, int mrows) {
    extern __shared__ char smem[];
    uint32_t sb = smem_u32(smem);
    int tid = threadIdx.x, lane = tid & 31, wid = tid >> 5;
    int wm = (wid & 1) * 64;        // warp M offset in tile
    int wn = (wid >> 1) * 32;       // warp N offset in tile
    int m0 = blockIdx.y * 128;
    int n0 = blockIdx.x * 128;

    float acc[4][4][4];
#pragma unroll
    for (int i = 0; i < 4; i++)
#pragma unroll
        for (int j = 0; j < 4; j++)
#pragma unroll
            for (int k = 0; k < 4; k++) acc[i][j][k] = 0.f;

    // ---- async tile loader: 2048 16B units (4 operands x 128 rows x 4 units) ----
#define LOAD_CHUNK(kc, buf)                                                          \
    do {                                                                             \
        _Pragma("unroll")                                                            \
        for (int i_ = 0; i_ < 8; i_++) {                                             \
            int u_ = tid + i_ * 256;                                                 \
            int tl_ = u_ >> 9;                                                       \
            int q_ = u_ & 511;                                                       \
            int r_ = q_ >> 2;                                                        \
            int c_ = q_ & 3;                                                         \
            const __nv_bfloat16* src_ = (tl_ == 0) ? Ahi : (tl_ == 1) ? Alo          \
                                       : (tl_ == 2) ? Bhi : Blo;                     \
            int grow_ = ((tl_ < 2) ? m0 : n0) + r_;                                  \
            const void* gp_ = src_ + (size_t)grow_ * EE + (kc) * BK + c_ * 8;        \
            uint32_t sp_ = sb + (buf) * BUFB + tl_ * OPB + r_ * SR + c_ * 16;        \
            CP_ASYNC16(sp_, gp_);                                                    \
        }                                                                            \
        asm volatile("cp.async.commit_group;");                                      \
    } while (0)

    LOAD_CHUNK(0, 0);

    for (int kc = 0; kc < 16; kc++) {
        int buf = kc & 1;
        if (kc < 15) {
            LOAD_CHUNK(kc + 1, buf ^ 1);
            asm volatile("cp.async.wait_group 1;");
        } else {
            asm volatile("cp.async.wait_group 0;");
        }
        __syncthreads();

        uint32_t base = sb + buf * BUFB;
#pragma unroll
        for (int ks = 0; ks < 2; ks++) {
            int kk = ks * 32;   // byte offset of k16 step (16 bf16 = 32B)
            uint32_t ah[4][4], al[4][4];
#pragma unroll
            for (int mi = 0; mi < 4; mi++) {
                uint32_t ra = base + (uint32_t)(wm + mi * 16 + (lane & 15)) * SR
                            + kk + ((lane >> 4) << 4);
                LDSM4(ah[mi], ra);
                LDSM4(al[mi], ra + OPB);
            }
#pragma unroll
            for (int ni = 0; ni < 4; ni++) {
                uint32_t rb = base + 2 * OPB
                            + (uint32_t)(wn + ni * 8 + (lane & 7)) * SR
                            + kk + (((lane >> 3) & 1) << 4);
                uint32_t bh[2], bl[2];
                LDSM2(bh, rb);
                LDSM2(bl, rb + OPB);
#pragma unroll
                for (int mi = 0; mi < 4; mi++) {
                    MMA_BF16(acc[mi][ni], ah[mi], bh);
                    MMA_BF16(acc[mi][ni], ah[mi], bl);
                    MMA_BF16(acc[mi][ni], al[mi], bh);
                }
            }
        }
        __syncthreads();
    }

    // ---- epilogue ----
#pragma unroll
    for (int ni = 0; ni < 4; ni++) {
        int c0 = n0 + wn + ni * 8 + (lane & 3) * 2;
        float b0 = bias1[c0], b1 = bias1[c0 + 1];
        if (bias2) { b0 += bias2[c0]; b1 += bias2[c0 + 1]; }
#pragma unroll
        for (int mi = 0; mi < 4; mi++) {
            int r0 = m0 + wm + mi * 16 + (lane >> 2);
            float* p = C + (size_t)r0 * ldc + c0;
            if (r0 < mrows) {
                float2 v = make_float2(acc[mi][ni][0] + b0, acc[mi][ni][1] + b1);
                *(float2*)p = v;
            }
            if (r0 + 8 < mrows) {
                float2 v = make_float2(acc[mi][ni][2] + b0, acc[mi][ni][3] + b1);
                *(float2*)(p + (size_t)8 * ldc) = v;
            }
        }
    }
}

// ================= fp32 -> (bf16 hi, bf16 lo) split =================
__global__ void split_kernel(const float* __restrict__ src,
                             __nv_bfloat16* __restrict__ hi,
                             __nv_bfloat16* __restrict__ lo, int n4) {
    int i = blockIdx.x * blockDim.x + threadIdx.x;
    if (i >= n4) return;
    float4 v = ((const float4*)src)[i];
    __nv_bfloat16 h0, h1, h2, h3, l0, l1, l2, l3;
    bf16_split(v.x, h0, l0); bf16_split(v.y, h1, l1);
    bf16_split(v.z, h2, l2); bf16_split(v.w, h3, l3);
    ((__nv_bfloat162*)hi)[2 * i + 0] = __halves2bfloat162(h0, h1);
    ((__nv_bfloat162*)hi)[2 * i + 1] = __halves2bfloat162(h2, h3);
    ((__nv_bfloat162*)lo)[2 * i + 0] = __halves2bfloat162(l0, l1);
    ((__nv_bfloat162*)lo)[2 * i + 1] = __halves2bfloat162(l2, l3);
}

// ================= embedding gather: split emb; seq row 0 =================
__global__ void gather_kernel(const int* __restrict__ captions,
                              const float* __restrict__ W_emb) {
    int idx = blockIdx.x * blockDim.x + threadIdx.x;
    if (idx >= TT * BB * EE) return;
    int e = idx % EE;
    int b = (idx / EE) % BB;
    int t = idx / (EE * BB);
    float v = W_emb[(size_t)captions[b * TT + t] * EE + e];
    __nv_bfloat16 h, l;
    bf16_split(v, h, l);
    g_Ehi[idx] = h;
    g_Elo[idx] = l;
    if (t == 0) {                               // seq[:,0] = emb[:,0]
        size_t s = ((size_t)b * TT) * EE + e;
        g_Shi[s] = h;
        g_Slo[s] = l;
    }
}

// ================= h=0, c=features, barrier slots = 0 =================
__global__ void init_state_kernel(const float* __restrict__ features) {
    int idx = blockIdx.x * blockDim.x + threadIdx.x;
    if (idx < BB * EE) { g_h[idx] = 0.f; g_c[idx] = features[idx]; }
    if (idx < 64) g_bars[idx] = 0u;
}

// ================= persistent LSTM: all 19 steps in one kernel =================
// 128 CTAs x 256 thr. Per step: split-K=4 fp32 GEMM (h @ W_hh^T, atomics into
// g_xgates which already holds x@W_ih^T + biases) -> grid barrier -> pointwise
// (writes h, c, and bf16 split of h into g_Shi/g_Slo) -> grid barrier.
__device__ __forceinline__ void gridbar(int slot) {
    __syncthreads();
    __threadfence();
    if (threadIdx.x == 0) {
        atomicAdd(&g_bars[slot], 1u);
        while (*(volatile unsigned*)&g_bars[slot] < 128u) {}
    }
    __syncthreads();
    __threadfence();
}

__global__ __launch_bounds__(256) void lstm_persist_kernel(const float* __restrict__ W_hh) {
    __shared__ float Xs[64][36];
    __shared__ float Ws[64][36];
    int blk = blockIdx.x;
    int tid = threadIdx.x;
    int n0 = (blk & 31) * 64;
    int koff = (blk >> 5) * 128;
    int tx = tid & 15, ty = tid >> 4;

    for (int t = 1; t < TT; t++) {
        // ---- phase A: gates[(t-1)] += h @ W_hh^T (this block's 64x64xK128 slice) ----
        float acc[4][4] = {};
        for (int kc = 0; kc < 128; kc += 32) {
#pragma unroll
            for (int i = 0; i < 2; i++) {
                int q = tid + i * 256;
                int r = q >> 3;
                int kk = (q & 7) << 2;
                *(float4*)(&Xs[r][kk]) = *(const float4*)(g_h + (size_t)r * EE + koff + kc + kk);
                *(float4*)(&Ws[r][kk]) =
                    *(const float4*)(W_hh + (size_t)(n0 + r) * EE + koff + kc + kk);
            }
            __syncthreads();
#pragma unroll
            for (int k4 = 0; k4 < 8; k4++) {
                float4 xr[4], wr[4];
#pragma unroll
                for (int i = 0; i < 4; i++) xr[i] = *(const float4*)(&Xs[ty * 4 + i][k4 * 4]);
#pragma unroll
                for (int j = 0; j < 4; j++) wr[j] = *(const float4*)(&Ws[tx * 4 + j][k4 * 4]);
#pragma unroll
                for (int i = 0; i < 4; i++)
#pragma unroll
                    for (int j = 0; j < 4; j++)
                        acc[i][j] += xr[i].x * wr[j].x + xr[i].y * wr[j].y
                                   + xr[i].z * wr[j].z + xr[i].w * wr[j].w;
            }
            __syncthreads();
        }
#pragma unroll
        for (int i = 0; i < 4; i++)
#pragma unroll
            for (int j = 0; j < 4; j++)
                atomicAdd(&g_xgates[((size_t)(t - 1) * BB + ty * 4 + i) * G4 + n0 + tx * 4 + j],
                          acc[i][j]);

        gridbar(2 * (t - 1));

        // ---- phase B: pointwise (one element per thread) ----
        {
            int idx = blk * 256 + tid;          // 0..32767
            int bb = idx >> 9, n = idx & 511;
            const float* gp = g_xgates + ((size_t)(t - 1) * BB + bb) * G4 + n;
            float gi = gp[0];
            float gf = gp[EE];
            float gg = gp[2 * EE];
            float go = gp[3 * EE];
            float iv = 1.f / (1.f + expf(-gi));
            float fv = 1.f / (1.f + expf(-gf));
            float gv = tanhf(gg);
            float ov = 1.f / (1.f + expf(-go));
            float c = fv * g_c[idx] + iv * gv;
            g_c[idx] = c;
            float h = ov * tanhf(c);
            g_h[idx] = h;
            __nv_bfloat16 hh, hl;
            bf16_split(h, hh, hl);
            size_t s = ((size_t)bb * TT + t) * EE + n;
            g_Shi[s] = hh;
            g_Slo[s] = hl;
        }

        if (t < TT - 1) gridbar(2 * (t - 1) + 1);
    }
}

// ================= launch =================
extern "C" void kernel_launch(void* const* d_in, const int* in_sizes, int n_in,
                              void* d_out, int out_size) {
    const float* features = (const float*)d_in[0];
    const int*   captions = (const int*)d_in[1];
    const float* W_emb    = (const float*)d_in[2];
    const float* W_out    = (const float*)d_in[3];
    const float* b_out    = (const float*)d_in[4];
    const float* W_ih     = (const float*)d_in[5];
    const float* W_hh     = (const float*)d_in[6];
    const float* b_ih     = (const float*)d_in[7];
    const float* b_hh     = (const float*)d_in[8];
    float* out = (float*)d_out;

    cudaFuncSetAttribute(hmma_gemm_kernel, cudaFuncAttributeMaxDynamicSharedMemorySize, SMEMB);

    void *pEhi, *pElo, *pShi, *pSlo, *pWoH, *pWoL, *pWiH, *pWiL, *pXg;
    cudaGetSymbolAddress(&pEhi, g_Ehi);
    cudaGetSymbolAddress(&pElo, g_Elo);
    cudaGetSymbolAddress(&pShi, g_Shi);
    cudaGetSymbolAddress(&pSlo, g_Slo);
    cudaGetSymbolAddress(&pWoH, g_WoutHi);
    cudaGetSymbolAddress(&pWoL, g_WoutLo);
    cudaGetSymbolAddress(&pWiH, g_WihHi);
    cudaGetSymbolAddress(&pWiL, g_WihLo);
    cudaGetSymbolAddress(&pXg, g_xgates);

    gather_kernel<<<(TT * BB * EE + 255) / 256, 256>>>(captions, W_emb);
    init_state_kernel<<<(BB * EE + 255) / 256, 256>>>(features);

    // x-part of all LSTM steps: xgates = emb @ W_ih^T + b_ih + b_hh  (tensor cores)
    split_kernel<<<(G4 * EE / 4 + 255) / 256, 256>>>(W_ih,
        (__nv_bfloat16*)pWiH, (__nv_bfloat16*)pWiL, G4 * EE / 4);
    hmma_gemm_kernel<<<dim3(G4 / 128, (NSTEP * BB + 127) / 128), 256, SMEMB>>>(
        (const __nv_bfloat16*)pEhi, (const __nv_bfloat16*)pElo,
        (const __nv_bfloat16*)pWiH, (const __nv_bfloat16*)pWiL,
        (float*)pXg, G4, b_ih, b_hh, NSTEP * BB);

    // W_out split (independent; overlaps nothing serially but cheap)
    split_kernel<<<((int)((size_t)VV * EE / 4) + 255) / 256, 256>>>(W_out,
        (__nv_bfloat16*)pWoH, (__nv_bfloat16*)pWoL, (int)((size_t)VV * EE / 4));

    // serial LSTM (recurrent half), one persistent kernel
    lstm_persist_kernel<<<128, 256>>>(W_hh);

    // projection: out = seq @ W_out^T + b_out  (tensor cores)
    hmma_gemm_kernel<<<dim3(VV / 128, (TT * BB) / 128), 256, SMEMB>>>(
        (const __nv_bfloat16*)pShi, (const __nv_bfloat16*)pSlo,
        (const __nv_bfloat16*)pWoH, (const __nv_bfloat16*)pWoL,
        out, VV, b_out, nullptr, TT * BB);
}

// round 8
// speedup vs baseline: 1.8839x; 1.0356x over previous
#include <cuda_runtime.h>
#include <cuda_bf16.h>
#include <math.h>
#include <stdint.h>

#define BB 64
#define TT 20
#define EE 512
#define VV 32000
#define G4 2048   // 4*EE
#define NSTEP (TT - 1)

// ---------------- scratch (no allocations allowed) ----------------
__device__ float g_h[BB * EE];
__device__ float g_c[BB * EE];
__device__ float g_xgates[NSTEP * BB * G4];      // [(t-1)*64+b][4E]
__device__ unsigned g_bars[64];                  // grid-barrier slots (zeroed per call)
__device__ __nv_bfloat16 g_Ehi[TT * BB * EE];    // emb split [t*64+b][e]
__device__ __nv_bfloat16 g_Elo[TT * BB * EE];
__device__ __nv_bfloat16 g_Shi[BB * TT * EE];    // seq split [b*20+t][e] (proj A operand)
__device__ __nv_bfloat16 g_Slo[BB * TT * EE];
__device__ __nv_bfloat16 g_WoutHi[(size_t)VV * EE];
__device__ __nv_bfloat16 g_WoutLo[(size_t)VV * EE];
__device__ __nv_bfloat16 g_WihHi[G4 * EE];
__device__ __nv_bfloat16 g_WihLo[G4 * EE];

// ================= helpers =================
__device__ __forceinline__ uint32_t smem_u32(const void* p) {
    uint32_t a;
    asm("{ .reg .u64 t; cvta.to.shared.u64 t, %1; cvt.u32.u64 %0, t; }" : "=r"(a) : "l"(p));
    return a;
}
__device__ __forceinline__ void bf16_split(float v, __nv_bfloat16& h, __nv_bfloat16& l) {
    h = __float2bfloat16(v);
    l = __float2bfloat16(v - __bfloat162float(h));
}

#define LDSM4(r, a)                                                            \
    asm volatile("ldmatrix.sync.aligned.m8n8.x4.shared.b16 {%0,%1,%2,%3}, [%4];" \
        : "=r"((r)[0]), "=r"((r)[1]), "=r"((r)[2]), "=r"((r)[3]) : "r"(a))
#define LDSM2(r, a)                                                            \
    asm volatile("ldmatrix.sync.aligned.m8n8.x2.shared.b16 {%0,%1}, [%2];"     \
        : "=r"((r)[0]), "=r"((r)[1]) : "r"(a))
#define MMA_BF16(acc, a, b)                                                    \
    asm volatile("mma.sync.aligned.m16n8k16.row.col.f32.bf16.bf16.f32 "        \
        "{%0,%1,%2,%3}, {%4,%5,%6,%7}, {%8,%9}, {%0,%1,%2,%3};"                \
        : "+f"((acc)[0]), "+f"((acc)[1]), "+f"((acc)[2]), "+f"((acc)[3])       \
        : "r"((a)[0]), "r"((a)[1]), "r"((a)[2]), "r"((a)[3]),                  \
          "r"((b)[0]), "r"((b)[1]))
#define CP_ASYNC16(sp, gp)                                                     \
    asm volatile("cp.async.cg.shared.global [%0], [%1], 16;" :: "r"(sp), "l"(gp))

// ================= HMMA bf16-split GEMM =================
// C[m0:128, n0:128] = Ahi*Bhi + Ahi*Blo + Alo*Bhi  (A [*,512] row-major, B [N,512] row-major)
// K = 512 fixed. bias1 (+bias2) added. Store guarded by m < mrows.
// blockIdx.x = M tile (fast dim -> A stays L2-resident; B tile shared by the
// concurrent m-tiles), blockIdx.y = N tile.
#define BK 32
#define SR 80                  // smem row stride bytes (64B data + 16B pad)
#define OPB (128 * SR)         // bytes per operand tile (10240)
#define BUFB (4 * OPB)         // per buffer (40960)
#define SMEMB (2 * BUFB)       // 81920

__global__ __launch_bounds__(256, 2) void hmma_gemm_kernel(
        const __nv_bfloat16* __restrict__ Ahi, const __nv_bfloat16* __restrict__ Alo,
        const __nv_bfloat16* __restrict__ Bhi, const __nv_bfloat16* __restrict__ Blo,
        float* __restrict__ C, int ldc,
        const float* __restrict__ bias1, const float* __restrict__ bias2, int mrows) {
    extern __shared__ char smem[];
    uint32_t sb = smem_u32(smem);
    int tid = threadIdx.x, lane = tid & 31, wid = tid >> 5;
    int wm = (wid & 1) * 64;        // warp M offset in tile
    int wn = (wid >> 1) * 32;       // warp N offset in tile
    int m0 = blockIdx.x * 128;
    int n0 = blockIdx.y * 128;

    float acc[4][4][4];
#pragma unroll
    for (int i = 0; i < 4; i++)
#pragma unroll
        for (int j = 0; j < 4; j++)
#pragma unroll
            for (int k = 0; k < 4; k++) acc[i][j][k] = 0.f;

    // ---- async tile loader: 2048 16B units (4 operands x 128 rows x 4 units) ----
#define LOAD_CHUNK(kc, buf)                                                          \
    do {                                                                             \
        _Pragma("unroll")                                                            \
        for (int i_ = 0; i_ < 8; i_++) {                                             \
            int u_ = tid + i_ * 256;                                                 \
            int tl_ = u_ >> 9;                                                       \
            int q_ = u_ & 511;                                                       \
            int r_ = q_ >> 2;                                                        \
            int c_ = q_ & 3;                                                         \
            const __nv_bfloat16* src_ = (tl_ == 0) ? Ahi : (tl_ == 1) ? Alo          \
                                       : (tl_ == 2) ? Bhi : Blo;                     \
            int grow_ = ((tl_ < 2) ? m0 : n0) + r_;                                  \
            const void* gp_ = src_ + (size_t)grow_ * EE + (kc) * BK + c_ * 8;        \
            uint32_t sp_ = sb + (buf) * BUFB + tl_ * OPB + r_ * SR + c_ * 16;        \
            CP_ASYNC16(sp_, gp_);                                                    \
        }                                                                            \
        asm volatile("cp.async.commit_group;");                                      \
    } while (0)

    LOAD_CHUNK(0, 0);

    for (int kc = 0; kc < 16; kc++) {
        int buf = kc & 1;
        if (kc < 15) {
            LOAD_CHUNK(kc + 1, buf ^ 1);
            asm volatile("cp.async.wait_group 1;");
        } else {
            asm volatile("cp.async.wait_group 0;");
        }
        __syncthreads();

        uint32_t base = sb + buf * BUFB;
#pragma unroll
        for (int ks = 0; ks < 2; ks++) {
            int kk = ks * 32;   // byte offset of k16 step (16 bf16 = 32B)
            uint32_t ah[4][4], al[4][4];
#pragma unroll
            for (int mi = 0; mi < 4; mi++) {
                uint32_t ra = base + (uint32_t)(wm + mi * 16 + (lane & 15)) * SR
                            + kk + ((lane >> 4) << 4);
                LDSM4(ah[mi], ra);
                LDSM4(al[mi], ra + OPB);
            }
#pragma unroll
            for (int ni = 0; ni < 4; ni++) {
                uint32_t rb = base + 2 * OPB
                            + (uint32_t)(wn + ni * 8 + (lane & 7)) * SR
                            + kk + (((lane >> 3) & 1) << 4);
                uint32_t bh[2], bl[2];
                LDSM2(bh, rb);
                LDSM2(bl, rb + OPB);
#pragma unroll
                for (int mi = 0; mi < 4; mi++) {
                    MMA_BF16(acc[mi][ni], ah[mi], bh);
                    MMA_BF16(acc[mi][ni], ah[mi], bl);
                    MMA_BF16(acc[mi][ni], al[mi], bh);
                }
            }
        }
        __syncthreads();
    }

    // ---- epilogue ----
#pragma unroll
    for (int ni = 0; ni < 4; ni++) {
        int c0 = n0 + wn + ni * 8 + (lane & 3) * 2;
        float b0 = bias1[c0], b1 = bias1[c0 + 1];
        if (bias2) { b0 += bias2[c0]; b1 += bias2[c0 + 1]; }
#pragma unroll
        for (int mi = 0; mi < 4; mi++) {
            int r0 = m0 + wm + mi * 16 + (lane >> 2);
            float* p = C + (size_t)r0 * ldc + c0;
            if (r0 < mrows) {
                float2 v = make_float2(acc[mi][ni][0] + b0, acc[mi][ni][1] + b1);
                *(float2*)p = v;
            }
            if (r0 + 8 < mrows) {
                float2 v = make_float2(acc[mi][ni][2] + b0, acc[mi][ni][3] + b1);
                *(float2*)(p + (size_t)8 * ldc) = v;
            }
        }
    }
}

// ================= fp32 -> (bf16 hi, bf16 lo) split =================
__global__ void split_kernel(const float* __restrict__ src,
                             __nv_bfloat16* __restrict__ hi,
                             __nv_bfloat16* __restrict__ lo, int n4) {
    int i = blockIdx.x * blockDim.x + threadIdx.x;
    if (i >= n4) return;
    float4 v = ((const float4*)src)[i];
    __nv_bfloat16 h0, h1, h2, h3, l0, l1, l2, l3;
    bf16_split(v.x, h0, l0); bf16_split(v.y, h1, l1);
    bf16_split(v.z, h2, l2); bf16_split(v.w, h3, l3);
    ((__nv_bfloat162*)hi)[2 * i + 0] = __halves2bfloat162(h0, h1);
    ((__nv_bfloat162*)hi)[2 * i + 1] = __halves2bfloat162(h2, h3);
    ((__nv_bfloat162*)lo)[2 * i + 0] = __halves2bfloat162(l0, l1);
    ((__nv_bfloat162*)lo)[2 * i + 1] = __halves2bfloat162(l2, l3);
}

// ================= embedding gather: split emb; seq row 0 =================
__global__ void gather_kernel(const int* __restrict__ captions,
                              const float* __restrict__ W_emb) {
    int idx = blockIdx.x * blockDim.x + threadIdx.x;
    if (idx >= TT * BB * EE) return;
    int e = idx % EE;
    int b = (idx / EE) % BB;
    int t = idx / (EE * BB);
    float v = W_emb[(size_t)captions[b * TT + t] * EE + e];
    __nv_bfloat16 h, l;
    bf16_split(v, h, l);
    g_Ehi[idx] = h;
    g_Elo[idx] = l;
    if (t == 0) {                               // seq[:,0] = emb[:,0]
        size_t s = ((size_t)b * TT) * EE + e;
        g_Shi[s] = h;
        g_Slo[s] = l;
    }
}

// ================= h=0, c=features, barrier slots = 0 =================
__global__ void init_state_kernel(const float* __restrict__ features) {
    int idx = blockIdx.x * blockDim.x + threadIdx.x;
    if (idx < BB * EE) { g_h[idx] = 0.f; g_c[idx] = features[idx]; }
    if (idx < 64) g_bars[idx] = 0u;
}

// ================= persistent LSTM: all 19 steps in one kernel =================
// 128 CTAs x 256 thr. Per step: split-K=4 fp32 GEMM (h @ W_hh^T, atomics into
// g_xgates which already holds x@W_ih^T + biases) -> grid barrier -> pointwise
// (writes h, c, and bf16 split of h into g_Shi/g_Slo) -> grid barrier.
// Step t=1 has h0 == 0: GEMM and its barrier are skipped (uniform across CTAs).
__device__ __forceinline__ void gridbar(int slot) {
    __syncthreads();
    __threadfence();
    if (threadIdx.x == 0) {
        atomicAdd(&g_bars[slot], 1u);
        while (*(volatile unsigned*)&g_bars[slot] < 128u) {}
    }
    __syncthreads();
    __threadfence();
}

__global__ __launch_bounds__(256) void lstm_persist_kernel(const float* __restrict__ W_hh) {
    __shared__ float Xs[64][36];
    __shared__ float Ws[64][36];
    int blk = blockIdx.x;
    int tid = threadIdx.x;
    int n0 = (blk & 31) * 64;
    int koff = (blk >> 5) * 128;
    int tx = tid & 15, ty = tid >> 4;

    for (int t = 1; t < TT; t++) {
        if (t > 1) {
            // ---- phase A: gates[(t-1)] += h @ W_hh^T (64x64 x K128 slice) ----
            float acc[4][4] = {};
            for (int kc = 0; kc < 128; kc += 32) {
#pragma unroll
                for (int i = 0; i < 2; i++) {
                    int q = tid + i * 256;
                    int r = q >> 3;
                    int kk = (q & 7) << 2;
                    *(float4*)(&Xs[r][kk]) =
                        *(const float4*)(g_h + (size_t)r * EE + koff + kc + kk);
                    *(float4*)(&Ws[r][kk]) =
                        *(const float4*)(W_hh + (size_t)(n0 + r) * EE + koff + kc + kk);
                }
                __syncthreads();
#pragma unroll
                for (int k4 = 0; k4 < 8; k4++) {
                    float4 xr[4], wr[4];
#pragma unroll
                    for (int i = 0; i < 4; i++) xr[i] = *(const float4*)(&Xs[ty * 4 + i][k4 * 4]);
#pragma unroll
                    for (int j = 0; j < 4; j++) wr[j] = *(const float4*)(&Ws[tx * 4 + j][k4 * 4]);
#pragma unroll
                    for (int i = 0; i < 4; i++)
#pragma unroll
                        for (int j = 0; j < 4; j++)
                            acc[i][j] += xr[i].x * wr[j].x + xr[i].y * wr[j].y
                                       + xr[i].z * wr[j].z + xr[i].w * wr[j].w;
                }
                __syncthreads();
            }
#pragma unroll
            for (int i = 0; i < 4; i++)
#pragma unroll
                for (int j = 0; j < 4; j++)
                    atomicAdd(&g_xgates[((size_t)(t - 1) * BB + ty * 4 + i) * G4
                                        + n0 + tx * 4 + j],
                              acc[i][j]);

            gridbar(2 * (t - 1));
        }

        // ---- phase B: pointwise (one element per thread) ----
        {
            int idx = blk * 256 + tid;          // 0..32767
            int bb = idx >> 9, n = idx & 511;
            const float* gp = g_xgates + ((size_t)(t - 1) * BB + bb) * G4 + n;
            float gi = gp[0];
            float gf = gp[EE];
            float gg = gp[2 * EE];
            float go = gp[3 * EE];
            float iv = 1.f / (1.f + expf(-gi));
            float fv = 1.f / (1.f + expf(-gf));
            float gv = tanhf(gg);
            float ov = 1.f / (1.f + expf(-go));
            float c = fv * g_c[idx] + iv * gv;
            g_c[idx] = c;
            float h = ov * tanhf(c);
            g_h[idx] = h;
            __nv_bfloat16 hh, hl;
            bf16_split(h, hh, hl);
            size_t s = ((size_t)bb * TT + t) * EE + n;
            g_Shi[s] = hh;
            g_Slo[s] = hl;
        }

        if (t < TT - 1) gridbar(2 * (t - 1) + 1);
    }
}

// ================= launch =================
extern "C" void kernel_launch(void* const* d_in, const int* in_sizes, int n_in,
                              void* d_out, int out_size) {
    const float* features = (const float*)d_in[0];
    const int*   captions = (const int*)d_in[1];
    const float* W_emb    = (const float*)d_in[2];
    const float* W_out    = (const float*)d_in[3];
    const float* b_out    = (const float*)d_in[4];
    const float* W_ih     = (const float*)d_in[5];
    const float* W_hh     = (const float*)d_in[6];
    const float* b_ih     = (const float*)d_in[7];
    const float* b_hh     = (const float*)d_in[8];
    float* out = (float*)d_out;

    cudaFuncSetAttribute(hmma_gemm_kernel, cudaFuncAttributeMaxDynamicSharedMemorySize, SMEMB);

    void *pEhi, *pElo, *pShi, *pSlo, *pWoH, *pWoL, *pWiH, *pWiL, *pXg;
    cudaGetSymbolAddress(&pEhi, g_Ehi);
    cudaGetSymbolAddress(&pElo, g_Elo);
    cudaGetSymbolAddress(&pShi, g_Shi);
    cudaGetSymbolAddress(&pSlo, g_Slo);
    cudaGetSymbolAddress(&pWoH, g_WoutHi);
    cudaGetSymbolAddress(&pWoL, g_WoutLo);
    cudaGetSymbolAddress(&pWiH, g_WihHi);
    cudaGetSymbolAddress(&pWiL, g_WihLo);
    cudaGetSymbolAddress(&pXg, g_xgates);

    gather_kernel<<<(TT * BB * EE + 255) / 256, 256>>>(captions, W_emb);
    init_state_kernel<<<(BB * EE + 255) / 256, 256>>>(features);

    // x-part of all LSTM steps: xgates = emb @ W_ih^T + b_ih + b_hh  (tensor cores)
    split_kernel<<<(G4 * EE / 4 + 255) / 256, 256>>>(W_ih,
        (__nv_bfloat16*)pWiH, (__nv_bfloat16*)pWiL, G4 * EE / 4);
    hmma_gemm_kernel<<<dim3((NSTEP * BB + 127) / 128, G4 / 128), 256, SMEMB>>>(
        (const __nv_bfloat16*)pEhi, (const __nv_bfloat16*)pElo,
        (const __nv_bfloat16*)pWiH, (const __nv_bfloat16*)pWiL,
        (float*)pXg, G4, b_ih, b_hh, NSTEP * BB);

    // W_out split (independent; cheap)
    split_kernel<<<((int)((size_t)VV * EE / 4) + 255) / 256, 256>>>(W_out,
        (__nv_bfloat16*)pWoH, (__nv_bfloat16*)pWoL, (int)((size_t)VV * EE / 4));

    // serial LSTM (recurrent half), one persistent kernel
    lstm_persist_kernel<<<128, 256>>>(W_hh);

    // projection: out = seq @ W_out^T + b_out  (tensor cores)
    hmma_gemm_kernel<<<dim3((TT * BB) / 128, VV / 128), 256, SMEMB>>>(
        (const __nv_bfloat16*)pShi, (const __nv_bfloat16*)pSlo,
        (const __nv_bfloat16*)pWoH, (const __nv_bfloat16*)pWoL,
        out, VV, b_out, nullptr, TT * BB);
}